// round 14
// baseline (speedup 1.0000x reference)
#include <cuda_runtime.h>
#include <cuda_bf16.h>

using u32 = unsigned int;
using u64 = unsigned long long;

#define BPAIR 4096
#define NROWS 8192
#define DDIM  512
// exp(x/T) = 2^(x * 2*log2(e)),  T = 0.5
#define EXP_SCALE 2.8853900817779268f
#define LN2_F     0.6931471805599453f

// ---------------- device scratch (no allocations allowed) ----------------
__device__ unsigned char g_nA[NROWS * DDIM];   // normalized [x1; z2], int8
__device__ unsigned char g_nB[NROWS * DDIM];   // normalized [x2; z1], int8
__device__ float g_scale[2 * NROWS];           // per-row dequant scale
__device__ float g_part[2 * 64 * NROWS];       // [mtx][slot 0..63][row] partials
__device__ float g_log_partial[128];
__device__ float g_pos_partial[1024];
__device__ unsigned int g_done;                // last-block counter (self-reset)

// ---------------- PTX helpers ----------------
__device__ __forceinline__ u32 smem_u32(const void* p) {
    u32 a;
    asm("{ .reg .u64 t; cvta.to.shared.u64 t, %1; cvt.u32.u64 %0, t; }"
        : "=r"(a) : "l"(p));
    return a;
}
__device__ __forceinline__ float ex2f(float x) {
    float y; asm("ex2.approx.f32 %0, %1;" : "=f"(y) : "f"(x)); return y;
}
__device__ __forceinline__ float lg2f(float x) {
    float y; asm("lg2.approx.f32 %0, %1;" : "=f"(y) : "f"(x)); return y;
}
__device__ __forceinline__ void cp_async16(u32 dst, const void* src) {
    asm volatile("cp.async.cg.shared.global [%0], [%1], 16;"
                 :: "r"(dst), "l"(src) : "memory");
}
#define CP_COMMIT() asm volatile("cp.async.commit_group;" ::: "memory")
#define CP_WAIT0()  asm volatile("cp.async.wait_group 0;" ::: "memory")
#define CP_WAIT1()  asm volatile("cp.async.wait_group 1;" ::: "memory")
#define CP_WAIT2()  asm volatile("cp.async.wait_group 2;" ::: "memory")

__device__ __forceinline__ void ldsm4(u32 (&r)[4], u32 addr) {
    asm volatile("ldmatrix.sync.aligned.m8n8.x4.shared.b16 {%0,%1,%2,%3}, [%4];"
        : "=r"(r[0]), "=r"(r[1]), "=r"(r[2]), "=r"(r[3]) : "r"(addr));
}
// INT8 MMA, K=32, s32 accumulate.
__device__ __forceinline__ void mmai16832(int (&d)[4], const u32 (&a)[4],
                                          u32 b0, u32 b1) {
    asm volatile(
        "mma.sync.aligned.m16n8k32.row.col.s32.s8.s8.s32 "
        "{%0,%1,%2,%3}, {%4,%5,%6,%7}, {%8,%9}, {%0,%1,%2,%3};"
        : "+r"(d[0]), "+r"(d[1]), "+r"(d[2]), "+r"(d[3])
        : "r"(a[0]), "r"(a[1]), "r"(a[2]), "r"(a[3]), "r"(b0), "r"(b1));
}

__device__ __forceinline__ u32 pack_s8x4(float a, float b, float c, float d) {
    int ia = __float2int_rn(a), ib = __float2int_rn(b);
    int ic = __float2int_rn(c), id = __float2int_rn(d);
    return (u32)(ia & 0xFF) | ((u32)(ib & 0xFF) << 8) |
           ((u32)(ic & 0xFF) << 16) | ((u32)id << 24);
}

// -------- kernel 1: fused normalize->int8 + pair dots (reads inputs once) --
__global__ void __launch_bounds__(256) k_norm_pos(
    const float* __restrict__ x1, const float* __restrict__ x2,
    const float* __restrict__ z1, const float* __restrict__ z2) {
    int wg   = blockIdx.x * 8 + (threadIdx.x >> 5);   // pair id 0..8191
    int lane = threadIdx.x & 31;
    int h = wg >> 12;
    int i = wg & (BPAIR - 1);
    const float* a = (h ? x2 : x1) + (size_t)i * DDIM;
    const float* b = (h ? z1 : z2) + (size_t)i * DDIM;
    unsigned char* matd = h ? g_nB : g_nA;

    float4 va[4], vb[4];
    float sd = 0.f, sa = 0.f, sb = 0.f, ma = 0.f, mb = 0.f;
#pragma unroll
    for (int k = 0; k < 4; k++) {
        va[k] = ((const float4*)a)[lane + 32 * k];
        vb[k] = ((const float4*)b)[lane + 32 * k];
        sd += va[k].x * vb[k].x + va[k].y * vb[k].y + va[k].z * vb[k].z + va[k].w * vb[k].w;
        sa += va[k].x * va[k].x + va[k].y * va[k].y + va[k].z * va[k].z + va[k].w * va[k].w;
        sb += vb[k].x * vb[k].x + vb[k].y * vb[k].y + vb[k].z * vb[k].z + vb[k].w * vb[k].w;
        ma = fmaxf(ma, fmaxf(fmaxf(fabsf(va[k].x), fabsf(va[k].y)),
                             fmaxf(fabsf(va[k].z), fabsf(va[k].w))));
        mb = fmaxf(mb, fmaxf(fmaxf(fabsf(vb[k].x), fabsf(vb[k].y)),
                             fmaxf(fabsf(vb[k].z), fabsf(vb[k].w))));
    }
#pragma unroll
    for (int o = 16; o; o >>= 1) {
        sd += __shfl_xor_sync(0xffffffffu, sd, o);
        sa += __shfl_xor_sync(0xffffffffu, sa, o);
        sb += __shfl_xor_sync(0xffffffffu, sb, o);
        ma = fmaxf(ma, __shfl_xor_sync(0xffffffffu, ma, o));
        mb = fmaxf(mb, __shfl_xor_sync(0xffffffffu, mb, o));
    }
    float ra = rsqrtf(sa), rb_ = rsqrtf(sb);
    float qa = 127.f / ma, qb = 127.f / mb;
    u32* da = (u32*)(matd + (size_t)i * DDIM);
    u32* db = (u32*)(matd + (size_t)(BPAIR + i) * DDIM);
#pragma unroll
    for (int k = 0; k < 4; k++) {
        da[lane + 32 * k] = pack_s8x4(va[k].x * qa, va[k].y * qa,
                                      va[k].z * qa, va[k].w * qa);
        db[lane + 32 * k] = pack_s8x4(vb[k].x * qb, vb[k].y * qb,
                                      vb[k].z * qb, vb[k].w * qb);
    }
    if (lane == 0) {
        g_scale[h * NROWS + i]         = ma * ra * (1.f / 127.f);
        g_scale[h * NROWS + BPAIR + i] = mb * rb_ * (1.f / 127.f);
    }
    __shared__ float sh[8];
    if (lane == 0) sh[threadIdx.x >> 5] = sd * ra * rb_;
    __syncthreads();
    if (threadIdx.x == 0) {
        float s = 0.f;
        for (int j = 0; j < 8; j++) s += sh[j];
        g_pos_partial[blockIdx.x] = s;
    }
    // PDL: allow the dependent GEMM grid to be staged
    cudaTriggerProgrammaticLaunchCompletion();
}

// ---------------- kernel 2: symmetric sim GEMM (int8, upper triangle) ------
// 148 CTAs x 512 threads (16 warps, warp grid 4M x 4N, warp tile 32x32).
// 4 warps per SMSP now cover MMA latency (issue slots were only ~31% busy
// at 2 warps/SMSP). Same smem layout / pipeline / partials as before.
#define SMEM_BYTES 200704
#define NTHR 512

__global__ void __launch_bounds__(NTHR, 1) k_simsum() {
    extern __shared__ char smem[];
    const int tid  = threadIdx.x;
    const int wid  = tid >> 5;
    const int lane = tid & 31;
    const int bx   = blockIdx.x;

    // tile range for this CTA: 16 CTAs get 29, 132 get 28
    const int t0 = bx * 28 + (bx < 16 ? bx : 16);
    const int nT = 28 + (bx < 16 ? 1 : 0);
    const int totalChunks = nT * 4;

    // decode compute cursor
    int c_m = t0 / 2080;
    int rrem = t0 % 2080;
    int c_rb = 0;
    while (rrem >= 64 - c_rb) { rrem -= 64 - c_rb; c_rb++; }
    int c_jt = c_rb + rrem;

    // prefetch cursor (B chunks; carries A prefetch on strip change)
    int p_m = c_m, p_rb = c_rb, p_jt = c_jt, p_cc = 0, p_q = 0, p_ab = 0;
    bool p_attach = false;
    int ab = 0;

    const u32 sb     = smem_u32(smem);
    float* rowred    = (float*)smem;            // 512 floats (4 warpN groups)
    float* colred    = rowred + 512;            // 512 floats (4 warpM groups)
    const u32 A_base = sb + 4096u;              // 2 bufs x 4 chunks x 16KB
    const u32 B_base = A_base + 131072u;        // 4 slots x 16KB

    const int warpM = wid >> 2, warpN = wid & 3;
    const int lx7 = lane & 7, l15 = lane & 15;
    const u32 aHi = (u32)(lane >> 4);
    const u32 bSegBit = (u32)((lane >> 3) & 1);
    const u32 aRowOff = (u32)(warpM * 32 + l15) * 128u;
    const u32 bRowOff = (u32)(warpN * 32 + lx7 + ((lane >> 4) << 3)) * 128u;
    const int qr = lane >> 2, qc = lane & 3;
    const int rowLo0 = warpM * 32 + qr;
    const int colB0  = warpN * 32 + qc * 2;

    // PDL: wait for k_norm_pos's writes (g_nA/g_nB/g_scale) to be visible
    cudaGridDependencySynchronize();

    // ---- prologue: A block for first strip into buf 0 (group 0) ----
    {
        const unsigned char* mp = c_m ? g_nB : g_nA;
        const unsigned char* abase = mp + (size_t)(c_rb * 128) * DDIM;
#pragma unroll
        for (int t = 0; t < 8; t++) {
            int idx = tid + t * NTHR;           // 0..4095
            int ch = idx >> 10, rem = idx & 1023, r = rem >> 3, sg = rem & 7;
            cp_async16(A_base + (u32)(ch * 16384 + r * 128 + ((sg ^ (r & 7)) << 4)),
                       abase + (size_t)r * DDIM + ch * 128 + sg * 16);
        }
        CP_COMMIT();
    }

    auto advancePF = [&]() {
        int orb = p_rb, om = p_m;
        p_jt++;
        if (p_jt == 64) { p_rb++; p_jt = p_rb; if (p_rb == 64) { p_m++; p_rb = 0; p_jt = 0; } }
        bool ns = (p_rb != orb) || (p_m != om);
        p_attach = ns;
        if (ns) p_ab ^= 1;
    };
    auto issuePF = [&]() {
        const unsigned char* mp = p_m ? g_nB : g_nA;
        u32 slot = B_base + (u32)(p_q & 3) * 16384u;
        const unsigned char* srcB = mp + (size_t)(p_jt * 128) * DDIM + p_cc * 128;
#pragma unroll
        for (int t = 0; t < 2; t++) {
            int idx = tid + t * NTHR;           // 0..1023
            int r = idx >> 3, sg = idx & 7;
            cp_async16(slot + (u32)(r * 128 + ((sg ^ (r & 7)) << 4)),
                       srcB + (size_t)r * DDIM + sg * 16);
        }
        if (p_attach) {   // A quarter p_cc of the new strip into buf p_ab
            u32 dstA = A_base + (u32)p_ab * 65536u + (u32)p_cc * 16384u;
            const unsigned char* srcA = mp + (size_t)(p_rb * 128) * DDIM + p_cc * 128;
#pragma unroll
            for (int t = 0; t < 2; t++) {
                int idx = tid + t * NTHR;
                int r = idx >> 3, sg = idx & 7;
                cp_async16(dstA + (u32)(r * 128 + ((sg ^ (r & 7)) << 4)),
                           srcA + (size_t)r * DDIM + sg * 16);
            }
        }
        CP_COMMIT();
        p_q++; p_cc++;
        if (p_cc == 4) { p_cc = 0; advancePF(); }
    };
    issuePF();
    issuePF();

    int acc[2][4][4];
#pragma unroll
    for (int mi = 0; mi < 2; mi++)
#pragma unroll
        for (int ni = 0; ni < 4; ni++)
#pragma unroll
            for (int e = 0; e < 4; e++) acc[mi][ni][e] = 0;

#pragma unroll 1
    for (int ti = 0; ti < nT; ti++) {
        const bool dg = (c_jt == c_rb);
        const int myM = c_m, myRb = c_rb, myJt = c_jt;

#pragma unroll 1
        for (int cc = 0; cc < 4; cc++) {
            const int q = ti * 4 + cc;
            if (q + 2 < totalChunks) { issuePF(); CP_WAIT2(); }
            else if (q + 1 < totalChunks) { CP_WAIT1(); }
            else { CP_WAIT0(); }
            __syncthreads();

            const u32 aChunk = A_base + (u32)ab * 65536u + (u32)cc * 16384u + aRowOff;
            const u32 bBase  = B_base + (u32)(q & 3) * 16384u + bRowOff;
#pragma unroll
            for (int ks = 0; ks < 4; ks++) {
                u32 A0[4], A1[4], B0[4], B1[4];
                const u32 aoff = (((2u * ks + aHi) ^ (u32)lx7) << 4);
                ldsm4(A0, aChunk + aoff);
                ldsm4(A1, aChunk + 2048u + aoff);
                const u32 boff = (((2u * ks + bSegBit) ^ (u32)lx7) << 4);
                ldsm4(B0, bBase + boff);
                ldsm4(B1, bBase + 2048u + boff);
                mmai16832(acc[0][0], A0, B0[0], B0[1]);
                mmai16832(acc[0][1], A0, B0[2], B0[3]);
                mmai16832(acc[0][2], A0, B1[0], B1[1]);
                mmai16832(acc[0][3], A0, B1[2], B1[3]);
                mmai16832(acc[1][0], A1, B0[0], B0[1]);
                mmai16832(acc[1][1], A1, B0[2], B0[3]);
                mmai16832(acc[1][2], A1, B1[0], B1[1]);
                mmai16832(acc[1][3], A1, B1[2], B1[3]);
            }
        }

        // ---- synchronous epilogue: dequant + exp + row/col sums ----
        {
            const float* gsc = g_scale + (size_t)myM * NROWS;
            float rsum[2][2] = {{0.f, 0.f}, {0.f, 0.f}};
            float csum[4][2];
#pragma unroll
            for (int ni = 0; ni < 4; ni++) { csum[ni][0] = 0.f; csum[ni][1] = 0.f; }
#pragma unroll
            for (int mi = 0; mi < 2; mi++) {
                float f0 = __ldg(gsc + myRb * 128 + rowLo0 + mi * 16) * EXP_SCALE;
                float f1 = __ldg(gsc + myRb * 128 + rowLo0 + mi * 16 + 8) * EXP_SCALE;
                const int rlo = rowLo0 + mi * 16, rhi = rlo + 8;
#pragma unroll
                for (int ni = 0; ni < 4; ni++) {
                    float s0 = __ldg(gsc + myJt * 128 + colB0 + ni * 8);
                    float s1 = __ldg(gsc + myJt * 128 + colB0 + ni * 8 + 1);
                    const int colb = colB0 + ni * 8;
                    float e0 = ex2f(__int2float_rn(acc[mi][ni][0]) * (f0 * s0));
                    float e1 = ex2f(__int2float_rn(acc[mi][ni][1]) * (f0 * s1));
                    float e2 = ex2f(__int2float_rn(acc[mi][ni][2]) * (f1 * s0));
                    float e3 = ex2f(__int2float_rn(acc[mi][ni][3]) * (f1 * s1));
                    if (dg) {
                        if (colb     == rlo) e0 = 0.f;
                        if (colb + 1 == rlo) e1 = 0.f;
                        if (colb     == rhi) e2 = 0.f;
                        if (colb + 1 == rhi) e3 = 0.f;
                    }
                    rsum[mi][0] += e0 + e1;
                    rsum[mi][1] += e2 + e3;
                    csum[ni][0] += e0 + e2;
                    csum[ni][1] += e1 + e3;
                    acc[mi][ni][0] = 0; acc[mi][ni][1] = 0;
                    acc[mi][ni][2] = 0; acc[mi][ni][3] = 0;
                }
            }
            // row reduce across quad columns (qc)
#pragma unroll
            for (int mi = 0; mi < 2; mi++)
#pragma unroll
                for (int h = 0; h < 2; h++) {
                    float v = rsum[mi][h];
                    v += __shfl_xor_sync(0xffffffffu, v, 1);
                    v += __shfl_xor_sync(0xffffffffu, v, 2);
                    if (qc == 0)
                        rowred[warpN * 128 + rowLo0 + mi * 16 + 8 * h] = v;
                }
            // col reduce across quad rows (qr)
#pragma unroll
            for (int ni = 0; ni < 4; ni++)
#pragma unroll
                for (int j = 0; j < 2; j++) {
                    float v = csum[ni][j];
                    v += __shfl_xor_sync(0xffffffffu, v, 4);
                    v += __shfl_xor_sync(0xffffffffu, v, 8);
                    v += __shfl_xor_sync(0xffffffffu, v, 16);
                    if (lane < 4)
                        colred[warpM * 128 + warpN * 32 + qc * 2 + ni * 8 + j] = v;
                }
            __syncthreads();
            float* gpart = g_part + (size_t)myM * 64 * NROWS;
            if (tid < 128) {
                float rv = (rowred[tid] + rowred[128 + tid]) +
                           (rowred[256 + tid] + rowred[384 + tid]);
                gpart[((size_t)myJt << 13) + myRb * 128 + tid] = rv;
                if (!dg) {
                    float cv = (colred[tid] + colred[128 + tid]) +
                               (colred[256 + tid] + colred[384 + tid]);
                    gpart[((size_t)myRb << 13) + myJt * 128 + tid] = cv;
                }
            }
            // next tile's first-chunk __syncthreads orders rowred/colred reuse
        }

        // advance compute cursor; flip A buffer on strip change
        int orb = c_rb, om = c_m;
        c_jt++;
        if (c_jt == 64) { c_rb++; c_jt = c_rb; if (c_rb == 64) { c_m++; c_rb = 0; c_jt = 0; } }
        if (c_rb != orb || c_m != om) ab ^= 1;
    }
    cudaTriggerProgrammaticLaunchCompletion();
}

// -------- kernel 3: per-row LSE + fused final reduction (last block) -------
__global__ void __launch_bounds__(128) k_lse_final(float* __restrict__ out) {
    const int bid = blockIdx.x;        // 0..127: mtx = bid>>6, blk = bid&63
    const int m = bid >> 6, blk = bid & 63;
    const int row = blk * 128 + threadIdx.x;

    // PDL: wait for k_simsum's g_part writes
    cudaGridDependencySynchronize();

    const float* gp = g_part + (size_t)m * 64 * NROWS;
    float S = 0.f;
#pragma unroll 8
    for (int s = 0; s < 64; s++) S += gp[((size_t)s << 13) + row];
    float lv = lg2f(S) * LN2_F;
    __shared__ float sh[4];
#pragma unroll
    for (int o = 16; o; o >>= 1) lv += __shfl_xor_sync(0xffffffffu, lv, o);
    if ((threadIdx.x & 31) == 0) sh[threadIdx.x >> 5] = lv;
    __syncthreads();
    if (threadIdx.x == 0)
        g_log_partial[bid] = (sh[0] + sh[1]) + (sh[2] + sh[3]);

    // last-block final reduction
    __threadfence();
    __shared__ unsigned int isLast;
    if (threadIdx.x == 0)
        isLast = (atomicAdd(&g_done, 1u) == 127u);
    __syncthreads();
    if (!isLast) return;
    __threadfence();

    const int t = threadIdx.x;
    float s = g_log_partial[t];                 // 128 elements, 1 per thread
    float p = 0.f;
#pragma unroll
    for (int i = 0; i < 8; i++) p += g_pos_partial[t + 128 * i];   // 1024 total
#pragma unroll
    for (int o = 16; o; o >>= 1) {
        s += __shfl_xor_sync(0xffffffffu, s, o);
        p += __shfl_xor_sync(0xffffffffu, p, o);
    }
    __shared__ float shs[4], shp[4];
    if ((t & 31) == 0) { shs[t >> 5] = s; shp[t >> 5] = p; }
    __syncthreads();
    if (t == 0) {
        float st = (shs[0] + shs[1]) + (shs[2] + shs[3]);
        float pt = (shp[0] + shp[1]) + (shp[2] + shp[3]);
        // loss = (sum LSE - (2/T)*sum pos) / (2B),  2/T = 4, 2B = 8192
        out[0] = (st - 4.0f * pt) / 8192.0f;
        g_done = 0;                              // reset for next graph replay
    }
}

extern "C" void kernel_launch(void* const* d_in, const int* in_sizes, int n_in,
                              void* d_out, int out_size) {
    const float* x1 = (const float*)d_in[0];
    const float* x2 = (const float*)d_in[1];
    const float* z1 = (const float*)d_in[2];
    const float* z2 = (const float*)d_in[3];
    float* out = (float*)d_out;

    cudaFuncSetAttribute(k_simsum, cudaFuncAttributeMaxDynamicSharedMemorySize,
                         SMEM_BYTES);

    k_norm_pos<<<1024, 256>>>(x1, x2, z1, z2);

    // k_simsum with PDL (pre-staged while k_norm_pos drains)
    {
        cudaLaunchConfig_t cfg = {};
        cfg.gridDim = dim3(148);
        cfg.blockDim = dim3(NTHR);
        cfg.dynamicSmemBytes = SMEM_BYTES;
        cfg.stream = 0;
        cudaLaunchAttribute attrs[1];
        attrs[0].id = cudaLaunchAttributeProgrammaticStreamSerialization;
        attrs[0].val.programmaticStreamSerializationAllowed = 1;
        cfg.attrs = attrs;
        cfg.numAttrs = 1;
        cudaLaunchKernelEx(&cfg, k_simsum);
    }

    // k_lse_final with PDL
    {
        cudaLaunchConfig_t cfg = {};
        cfg.gridDim = dim3(128);
        cfg.blockDim = dim3(128);
        cfg.dynamicSmemBytes = 0;
        cfg.stream = 0;
        cudaLaunchAttribute attrs[1];
        attrs[0].id = cudaLaunchAttributeProgrammaticStreamSerialization;
        attrs[0].val.programmaticStreamSerializationAllowed = 1;
        cfg.attrs = attrs;
        cfg.numAttrs = 1;
        cudaLaunchKernelEx(&cfg, k_lse_final, out);
    }
}

// round 17
// speedup vs baseline: 1.0560x; 1.0560x over previous
#include <cuda_runtime.h>
#include <cuda_bf16.h>

using u32 = unsigned int;
using u64 = unsigned long long;

#define BPAIR 4096
#define NROWS 8192
#define DDIM  512
// exp(x/T) = 2^(x * 2*log2(e)),  T = 0.5
#define EXP_SCALE 2.8853900817779268f
#define LN2_F     0.6931471805599453f

// ---------------- device scratch (no allocations allowed) ----------------
__device__ unsigned char g_nA[NROWS * DDIM];   // normalized [x1; z2], int8
__device__ unsigned char g_nB[NROWS * DDIM];   // normalized [x2; z1], int8
__device__ float g_scale[2 * NROWS];           // per-row dequant scale
__device__ float g_part[2 * 64 * NROWS];       // [mtx][slot 0..63][row] partials
__device__ float g_log_partial[128];
__device__ float g_pos_partial[1024];
__device__ unsigned int g_done;                // last-block counter (self-reset)

// ---------------- PTX helpers ----------------
__device__ __forceinline__ u32 smem_u32(const void* p) {
    u32 a;
    asm("{ .reg .u64 t; cvta.to.shared.u64 t, %1; cvt.u32.u64 %0, t; }"
        : "=r"(a) : "l"(p));
    return a;
}
__device__ __forceinline__ float ex2f(float x) {
    float y; asm("ex2.approx.f32 %0, %1;" : "=f"(y) : "f"(x)); return y;
}
__device__ __forceinline__ float lg2f(float x) {
    float y; asm("lg2.approx.f32 %0, %1;" : "=f"(y) : "f"(x)); return y;
}
__device__ __forceinline__ void cp_async16(u32 dst, const void* src) {
    asm volatile("cp.async.cg.shared.global [%0], [%1], 16;"
                 :: "r"(dst), "l"(src) : "memory");
}
#define CP_COMMIT() asm volatile("cp.async.commit_group;" ::: "memory")
#define CP_WAIT0()  asm volatile("cp.async.wait_group 0;" ::: "memory")
#define CP_WAIT1()  asm volatile("cp.async.wait_group 1;" ::: "memory")
#define CP_WAIT2()  asm volatile("cp.async.wait_group 2;" ::: "memory")

__device__ __forceinline__ void ldsm4(u32 (&r)[4], u32 addr) {
    asm volatile("ldmatrix.sync.aligned.m8n8.x4.shared.b16 {%0,%1,%2,%3}, [%4];"
        : "=r"(r[0]), "=r"(r[1]), "=r"(r[2]), "=r"(r[3]) : "r"(addr));
}
// INT8 MMA, K=32, s32 accumulate.
__device__ __forceinline__ void mmai16832(int (&d)[4], const u32 (&a)[4],
                                          u32 b0, u32 b1) {
    asm volatile(
        "mma.sync.aligned.m16n8k32.row.col.s32.s8.s8.s32 "
        "{%0,%1,%2,%3}, {%4,%5,%6,%7}, {%8,%9}, {%0,%1,%2,%3};"
        : "+r"(d[0]), "+r"(d[1]), "+r"(d[2]), "+r"(d[3])
        : "r"(a[0]), "r"(a[1]), "r"(a[2]), "r"(a[3]), "r"(b0), "r"(b1));
}

__device__ __forceinline__ u32 pack_s8x4(float a, float b, float c, float d) {
    int ia = __float2int_rn(a), ib = __float2int_rn(b);
    int ic = __float2int_rn(c), id = __float2int_rn(d);
    return (u32)(ia & 0xFF) | ((u32)(ib & 0xFF) << 8) |
           ((u32)(ic & 0xFF) << 16) | ((u32)id << 24);
}

// -------- kernel 1: fused normalize->int8 + pair dots (reads inputs once) --
__global__ void __launch_bounds__(256) k_norm_pos(
    const float* __restrict__ x1, const float* __restrict__ x2,
    const float* __restrict__ z1, const float* __restrict__ z2) {
    int wg   = blockIdx.x * 8 + (threadIdx.x >> 5);   // pair id 0..8191
    int lane = threadIdx.x & 31;
    int h = wg >> 12;
    int i = wg & (BPAIR - 1);
    const float* a = (h ? x2 : x1) + (size_t)i * DDIM;
    const float* b = (h ? z1 : z2) + (size_t)i * DDIM;
    unsigned char* matd = h ? g_nB : g_nA;

    float4 va[4], vb[4];
    float sd = 0.f, sa = 0.f, sb = 0.f, ma = 0.f, mb = 0.f;
#pragma unroll
    for (int k = 0; k < 4; k++) {
        va[k] = ((const float4*)a)[lane + 32 * k];
        vb[k] = ((const float4*)b)[lane + 32 * k];
        sd += va[k].x * vb[k].x + va[k].y * vb[k].y + va[k].z * vb[k].z + va[k].w * vb[k].w;
        sa += va[k].x * va[k].x + va[k].y * va[k].y + va[k].z * va[k].z + va[k].w * va[k].w;
        sb += vb[k].x * vb[k].x + vb[k].y * vb[k].y + vb[k].z * vb[k].z + vb[k].w * vb[k].w;
        ma = fmaxf(ma, fmaxf(fmaxf(fabsf(va[k].x), fabsf(va[k].y)),
                             fmaxf(fabsf(va[k].z), fabsf(va[k].w))));
        mb = fmaxf(mb, fmaxf(fmaxf(fabsf(vb[k].x), fabsf(vb[k].y)),
                             fmaxf(fabsf(vb[k].z), fabsf(vb[k].w))));
    }
#pragma unroll
    for (int o = 16; o; o >>= 1) {
        sd += __shfl_xor_sync(0xffffffffu, sd, o);
        sa += __shfl_xor_sync(0xffffffffu, sa, o);
        sb += __shfl_xor_sync(0xffffffffu, sb, o);
        ma = fmaxf(ma, __shfl_xor_sync(0xffffffffu, ma, o));
        mb = fmaxf(mb, __shfl_xor_sync(0xffffffffu, mb, o));
    }
    float ra = rsqrtf(sa), rb_ = rsqrtf(sb);
    float qa = 127.f / ma, qb = 127.f / mb;
    u32* da = (u32*)(matd + (size_t)i * DDIM);
    u32* db = (u32*)(matd + (size_t)(BPAIR + i) * DDIM);
#pragma unroll
    for (int k = 0; k < 4; k++) {
        da[lane + 32 * k] = pack_s8x4(va[k].x * qa, va[k].y * qa,
                                      va[k].z * qa, va[k].w * qa);
        db[lane + 32 * k] = pack_s8x4(vb[k].x * qb, vb[k].y * qb,
                                      vb[k].z * qb, vb[k].w * qb);
    }
    if (lane == 0) {
        g_scale[h * NROWS + i]         = ma * ra * (1.f / 127.f);
        g_scale[h * NROWS + BPAIR + i] = mb * rb_ * (1.f / 127.f);
    }
    __shared__ float sh[8];
    if (lane == 0) sh[threadIdx.x >> 5] = sd * ra * rb_;
    __syncthreads();
    if (threadIdx.x == 0) {
        float s = 0.f;
        for (int j = 0; j < 8; j++) s += sh[j];
        g_pos_partial[blockIdx.x] = s;
    }
    // PDL: allow the dependent GEMM grid to be staged
    cudaTriggerProgrammaticLaunchCompletion();
}

// ---------------- kernel 2: symmetric sim GEMM (int8, upper triangle) ------
// 148 CTAs x 256 threads (R13 winner config). 8 warps, warp grid 4M x 2N,
// warp tile 32x64. A row-blocks double-buffered; next strip's A rides in B
// commit groups. B via 4-slot 16KB ring, per-chunk commits, CP_WAIT2 depth.
// Fragment double-buffering in the k-step loop; synchronous per-tile epilogue.
#define SMEM_BYTES 200704

__global__ void __launch_bounds__(256, 1) k_simsum() {
    extern __shared__ char smem[];
    const int tid  = threadIdx.x;
    const int wid  = tid >> 5;
    const int lane = tid & 31;
    const int bx   = blockIdx.x;

    // tile range for this CTA: 16 CTAs get 29, 132 get 28
    const int t0 = bx * 28 + (bx < 16 ? bx : 16);
    const int nT = 28 + (bx < 16 ? 1 : 0);
    const int totalChunks = nT * 4;

    // decode compute cursor
    int c_m = t0 / 2080;
    int rrem = t0 % 2080;
    int c_rb = 0;
    while (rrem >= 64 - c_rb) { rrem -= 64 - c_rb; c_rb++; }
    int c_jt = c_rb + rrem;

    // prefetch cursor (B chunks; carries A prefetch on strip change)
    int p_m = c_m, p_rb = c_rb, p_jt = c_jt, p_cc = 0, p_q = 0, p_ab = 0;
    bool p_attach = false;
    int ab = 0;

    const u32 sb     = smem_u32(smem);
    float* rowred    = (float*)smem;            // 256 floats
    float* colred    = rowred + 256;            // 512 floats
    const u32 A_base = sb + 4096u;              // 2 bufs x 4 chunks x 16KB
    const u32 B_base = A_base + 131072u;        // 4 slots x 16KB

    const int warpM = wid >> 1, warpN = wid & 1;
    const int lx7 = lane & 7, l15 = lane & 15;
    const u32 aHi = (u32)(lane >> 4);
    const u32 bSegBit = (u32)((lane >> 3) & 1);
    const u32 aRowOff = (u32)(warpM * 32 + l15) * 128u;
    const u32 bRowOff = (u32)(warpN * 64 + lx7 + ((lane >> 4) << 3)) * 128u;
    const int qr = lane >> 2, qc = lane & 3;
    const int rowLo0 = warpM * 32 + qr;
    const int colB0  = warpN * 64 + qc * 2;

    // PDL: wait for k_norm_pos's writes (g_nA/g_nB/g_scale) to be visible
    cudaGridDependencySynchronize();

    // ---- prologue: A block for first strip into buf 0 (group 0) ----
    {
        const unsigned char* mp = c_m ? g_nB : g_nA;
        const unsigned char* abase = mp + (size_t)(c_rb * 128) * DDIM;
#pragma unroll
        for (int t = 0; t < 16; t++) {
            int idx = tid + t * 256;            // 0..4095
            int ch = idx >> 10, rem = idx & 1023, r = rem >> 3, sg = rem & 7;
            cp_async16(A_base + (u32)(ch * 16384 + r * 128 + ((sg ^ (r & 7)) << 4)),
                       abase + (size_t)r * DDIM + ch * 128 + sg * 16);
        }
        CP_COMMIT();
    }

    auto advancePF = [&]() {
        int orb = p_rb, om = p_m;
        p_jt++;
        if (p_jt == 64) { p_rb++; p_jt = p_rb; if (p_rb == 64) { p_m++; p_rb = 0; p_jt = 0; } }
        bool ns = (p_rb != orb) || (p_m != om);
        p_attach = ns;
        if (ns) p_ab ^= 1;
    };
    auto issuePF = [&]() {
        const unsigned char* mp = p_m ? g_nB : g_nA;
        u32 slot = B_base + (u32)(p_q & 3) * 16384u;
        const unsigned char* srcB = mp + (size_t)(p_jt * 128) * DDIM + p_cc * 128;
#pragma unroll
        for (int t = 0; t < 4; t++) {
            int idx = tid + t * 256;
            int r = idx >> 3, sg = idx & 7;
            cp_async16(slot + (u32)(r * 128 + ((sg ^ (r & 7)) << 4)),
                       srcB + (size_t)r * DDIM + sg * 16);
        }
        if (p_attach) {   // A quarter p_cc of the new strip into buf p_ab
            u32 dstA = A_base + (u32)p_ab * 65536u + (u32)p_cc * 16384u;
            const unsigned char* srcA = mp + (size_t)(p_rb * 128) * DDIM + p_cc * 128;
#pragma unroll
            for (int t = 0; t < 4; t++) {
                int idx = tid + t * 256;
                int r = idx >> 3, sg = idx & 7;
                cp_async16(dstA + (u32)(r * 128 + ((sg ^ (r & 7)) << 4)),
                           srcA + (size_t)r * DDIM + sg * 16);
            }
        }
        CP_COMMIT();
        p_q++; p_cc++;
        if (p_cc == 4) { p_cc = 0; advancePF(); }
    };
    issuePF();
    issuePF();

    int acc[2][8][4];
#pragma unroll
    for (int mi = 0; mi < 2; mi++)
#pragma unroll
        for (int ni = 0; ni < 8; ni++)
#pragma unroll
            for (int e = 0; e < 4; e++) acc[mi][ni][e] = 0;

#pragma unroll 1
    for (int ti = 0; ti < nT; ti++) {
        const bool dg = (c_jt == c_rb);
        const int myM = c_m, myRb = c_rb, myJt = c_jt;

#pragma unroll 1
        for (int cc = 0; cc < 4; cc++) {
            const int q = ti * 4 + cc;
            if (q + 2 < totalChunks) { issuePF(); CP_WAIT2(); }
            else if (q + 1 < totalChunks) { CP_WAIT1(); }
            else { CP_WAIT0(); }
            __syncthreads();

            const u32 aChunk = A_base + (u32)ab * 65536u + (u32)cc * 16384u + aRowOff;
            const u32 bBase  = B_base + (u32)(q & 3) * 16384u + bRowOff;

            // fragment double-buffer: load ks+1 while ks's MMAs issue
            u32 Af[2][2][4], Bf[2][4][4];
#define LDFRAGS(buf, ks) do {                                            \
            const u32 aoff_ = (((2u * (ks) + aHi) ^ (u32)lx7) << 4);     \
            ldsm4(Af[buf][0], aChunk + aoff_);                           \
            ldsm4(Af[buf][1], aChunk + 2048u + aoff_);                   \
            const u32 boff_ = (((2u * (ks) + bSegBit) ^ (u32)lx7) << 4); \
            ldsm4(Bf[buf][0], bBase + boff_);                            \
            ldsm4(Bf[buf][1], bBase + 2048u + boff_);                    \
            ldsm4(Bf[buf][2], bBase + 4096u + boff_);                    \
            ldsm4(Bf[buf][3], bBase + 6144u + boff_);                    \
        } while (0)

            LDFRAGS(0, 0);
#pragma unroll
            for (int ks = 0; ks < 4; ks++) {
                const int cur = ks & 1, nxt = cur ^ 1;
                if (ks < 3) LDFRAGS(nxt, ks + 1);
                mmai16832(acc[0][0], Af[cur][0], Bf[cur][0][0], Bf[cur][0][1]);
                mmai16832(acc[0][1], Af[cur][0], Bf[cur][0][2], Bf[cur][0][3]);
                mmai16832(acc[0][2], Af[cur][0], Bf[cur][1][0], Bf[cur][1][1]);
                mmai16832(acc[0][3], Af[cur][0], Bf[cur][1][2], Bf[cur][1][3]);
                mmai16832(acc[0][4], Af[cur][0], Bf[cur][2][0], Bf[cur][2][1]);
                mmai16832(acc[0][5], Af[cur][0], Bf[cur][2][2], Bf[cur][2][3]);
                mmai16832(acc[0][6], Af[cur][0], Bf[cur][3][0], Bf[cur][3][1]);
                mmai16832(acc[0][7], Af[cur][0], Bf[cur][3][2], Bf[cur][3][3]);
                mmai16832(acc[1][0], Af[cur][1], Bf[cur][0][0], Bf[cur][0][1]);
                mmai16832(acc[1][1], Af[cur][1], Bf[cur][0][2], Bf[cur][0][3]);
                mmai16832(acc[1][2], Af[cur][1], Bf[cur][1][0], Bf[cur][1][1]);
                mmai16832(acc[1][3], Af[cur][1], Bf[cur][1][2], Bf[cur][1][3]);
                mmai16832(acc[1][4], Af[cur][1], Bf[cur][2][0], Bf[cur][2][1]);
                mmai16832(acc[1][5], Af[cur][1], Bf[cur][2][2], Bf[cur][2][3]);
                mmai16832(acc[1][6], Af[cur][1], Bf[cur][3][0], Bf[cur][3][1]);
                mmai16832(acc[1][7], Af[cur][1], Bf[cur][3][2], Bf[cur][3][3]);
            }
#undef LDFRAGS
        }

        // ---- synchronous epilogue: dequant + exp + row/col sums ----
        {
            const float* gsc = g_scale + (size_t)myM * NROWS;
            float rsum[2][2] = {{0.f, 0.f}, {0.f, 0.f}};
            float csum[8][2];
#pragma unroll
            for (int ni = 0; ni < 8; ni++) { csum[ni][0] = 0.f; csum[ni][1] = 0.f; }
#pragma unroll
            for (int mi = 0; mi < 2; mi++) {
                float f0 = __ldg(gsc + myRb * 128 + rowLo0 + mi * 16) * EXP_SCALE;
                float f1 = __ldg(gsc + myRb * 128 + rowLo0 + mi * 16 + 8) * EXP_SCALE;
                const int rlo = rowLo0 + mi * 16, rhi = rlo + 8;
#pragma unroll
                for (int ni = 0; ni < 8; ni++) {
                    float s0 = __ldg(gsc + myJt * 128 + colB0 + ni * 8);
                    float s1 = __ldg(gsc + myJt * 128 + colB0 + ni * 8 + 1);
                    const int colb = colB0 + ni * 8;
                    float e0 = ex2f(__int2float_rn(acc[mi][ni][0]) * (f0 * s0));
                    float e1 = ex2f(__int2float_rn(acc[mi][ni][1]) * (f0 * s1));
                    float e2 = ex2f(__int2float_rn(acc[mi][ni][2]) * (f1 * s0));
                    float e3 = ex2f(__int2float_rn(acc[mi][ni][3]) * (f1 * s1));
                    if (dg) {
                        if (colb     == rlo) e0 = 0.f;
                        if (colb + 1 == rlo) e1 = 0.f;
                        if (colb     == rhi) e2 = 0.f;
                        if (colb + 1 == rhi) e3 = 0.f;
                    }
                    rsum[mi][0] += e0 + e1;
                    rsum[mi][1] += e2 + e3;
                    csum[ni][0] += e0 + e2;
                    csum[ni][1] += e1 + e3;
                    acc[mi][ni][0] = 0; acc[mi][ni][1] = 0;
                    acc[mi][ni][2] = 0; acc[mi][ni][3] = 0;
                }
            }
            // row reduce across quad columns (qc)
#pragma unroll
            for (int mi = 0; mi < 2; mi++)
#pragma unroll
                for (int h = 0; h < 2; h++) {
                    float v = rsum[mi][h];
                    v += __shfl_xor_sync(0xffffffffu, v, 1);
                    v += __shfl_xor_sync(0xffffffffu, v, 2);
                    if (qc == 0)
                        rowred[warpN * 128 + rowLo0 + mi * 16 + 8 * h] = v;
                }
            // col reduce across quad rows (qr)
#pragma unroll
            for (int ni = 0; ni < 8; ni++)
#pragma unroll
                for (int j = 0; j < 2; j++) {
                    float v = csum[ni][j];
                    v += __shfl_xor_sync(0xffffffffu, v, 4);
                    v += __shfl_xor_sync(0xffffffffu, v, 8);
                    v += __shfl_xor_sync(0xffffffffu, v, 16);
                    if (lane < 4)
                        colred[warpM * 128 + warpN * 64 + qc * 2 + ni * 8 + j] = v;
                }
            __syncthreads();
            float* gpart = g_part + (size_t)myM * 64 * NROWS;
            if (tid < 128) {
                float rv = rowred[tid] + rowred[128 + tid];
                gpart[((size_t)myJt << 13) + myRb * 128 + tid] = rv;
                if (!dg) {
                    float cv = colred[tid] + colred[128 + tid] +
                               colred[256 + tid] + colred[384 + tid];
                    gpart[((size_t)myRb << 13) + myJt * 128 + tid] = cv;
                }
            }
            // next tile's first-chunk __syncthreads orders rowred/colred reuse
        }

        // advance compute cursor; flip A buffer on strip change
        int orb = c_rb, om = c_m;
        c_jt++;
        if (c_jt == 64) { c_rb++; c_jt = c_rb; if (c_rb == 64) { c_m++; c_rb = 0; c_jt = 0; } }
        if (c_rb != orb || c_m != om) ab ^= 1;
    }
    cudaTriggerProgrammaticLaunchCompletion();
}

// -------- kernel 3: per-row LSE + fused final reduction (last block) -------
// 256 threads: halves split the 64 partial slots (2x MLP on the strided walk).
__global__ void __launch_bounds__(256) k_lse_final(float* __restrict__ out) {
    const int bid = blockIdx.x;        // 0..127: mtx = bid>>6, blk = bid&63
    const int m = bid >> 6, blk = bid & 63;
    const int half = threadIdx.x >> 7;            // 0 or 1
    const int t    = threadIdx.x & 127;
    const int row  = blk * 128 + t;

    // PDL: wait for k_simsum's g_part writes
    cudaGridDependencySynchronize();

    __shared__ float shp2[256];
    const float* gp = g_part + (size_t)m * 64 * NROWS + ((size_t)(half * 32) << 13);
    float S = 0.f;
#pragma unroll 8
    for (int s = 0; s < 32; s++) S += gp[((size_t)s << 13) + row];
    shp2[half * 128 + t] = S;
    __syncthreads();

    __shared__ float sh[4];
    if (threadIdx.x < 128) {
        float Sv = shp2[threadIdx.x] + shp2[128 + threadIdx.x];
        float lv = lg2f(Sv) * LN2_F;
#pragma unroll
        for (int o = 16; o; o >>= 1) lv += __shfl_xor_sync(0xffffffffu, lv, o);
        if ((threadIdx.x & 31) == 0) sh[threadIdx.x >> 5] = lv;
    }
    __syncthreads();
    if (threadIdx.x == 0)
        g_log_partial[bid] = (sh[0] + sh[1]) + (sh[2] + sh[3]);

    // last-block final reduction
    __threadfence();
    __shared__ unsigned int isLast;
    if (threadIdx.x == 0)
        isLast = (atomicAdd(&g_done, 1u) == 127u);
    __syncthreads();
    if (!isLast) return;
    __threadfence();

    __shared__ float shs[4], shp[4];
    if (threadIdx.x < 128) {
        const int tt = threadIdx.x;
        float s = g_log_partial[tt];              // 128 elements, 1 per thread
        float p = 0.f;
#pragma unroll
        for (int i = 0; i < 8; i++) p += g_pos_partial[tt + 128 * i];  // 1024
#pragma unroll
        for (int o = 16; o; o >>= 1) {
            s += __shfl_xor_sync(0xffffffffu, s, o);
            p += __shfl_xor_sync(0xffffffffu, p, o);
        }
        if ((tt & 31) == 0) { shs[tt >> 5] = s; shp[tt >> 5] = p; }
    }
    __syncthreads();
    if (threadIdx.x == 0) {
        float st = (shs[0] + shs[1]) + (shs[2] + shs[3]);
        float pt = (shp[0] + shp[1]) + (shp[2] + shp[3]);
        // loss = (sum LSE - (2/T)*sum pos) / (2B),  2/T = 4, 2B = 8192
        out[0] = (st - 4.0f * pt) / 8192.0f;
        g_done = 0;                              // reset for next graph replay
    }
}

extern "C" void kernel_launch(void* const* d_in, const int* in_sizes, int n_in,
                              void* d_out, int out_size) {
    const float* x1 = (const float*)d_in[0];
    const float* x2 = (const float*)d_in[1];
    const float* z1 = (const float*)d_in[2];
    const float* z2 = (const float*)d_in[3];
    float* out = (float*)d_out;

    cudaFuncSetAttribute(k_simsum, cudaFuncAttributeMaxDynamicSharedMemorySize,
                         SMEM_BYTES);

    k_norm_pos<<<1024, 256>>>(x1, x2, z1, z2);

    // k_simsum with PDL (pre-staged while k_norm_pos drains)
    {
        cudaLaunchConfig_t cfg = {};
        cfg.gridDim = dim3(148);
        cfg.blockDim = dim3(256);
        cfg.dynamicSmemBytes = SMEM_BYTES;
        cfg.stream = 0;
        cudaLaunchAttribute attrs[1];
        attrs[0].id = cudaLaunchAttributeProgrammaticStreamSerialization;
        attrs[0].val.programmaticStreamSerializationAllowed = 1;
        cfg.attrs = attrs;
        cfg.numAttrs = 1;
        cudaLaunchKernelEx(&cfg, k_simsum);
    }

    // k_lse_final with PDL
    {
        cudaLaunchConfig_t cfg = {};
        cfg.gridDim = dim3(128);
        cfg.blockDim = dim3(256);
        cfg.dynamicSmemBytes = 0;
        cfg.stream = 0;
        cudaLaunchAttribute attrs[1];
        attrs[0].id = cudaLaunchAttributeProgrammaticStreamSerialization;
        attrs[0].val.programmaticStreamSerializationAllowed = 1;
        cfg.attrs = attrs;
        cfg.numAttrs = 1;
        cudaLaunchKernelEx(&cfg, k_lse_final, out);
    }
}